// round 1
// baseline (speedup 1.0000x reference)
#include <cuda_runtime.h>

// ---------------- problem constants ----------------
#define BB   16
#define NN   2048
#define NSEQ (BB*NN)      // 32768
#define TT   48
#define EE   32
#define CC   64           // C0 == C1
#define H1   256
#define H2   128
#define NPRED 12

// scratch: last-row context per sequence (graph/alloc-rule safe)
__device__ float g_last[NSEQ * CC];

__device__ __forceinline__ float4 ldg4(const float* p) {
    return __ldg(reinterpret_cast<const float4*>(p));
}

// 3x8 register-tile FMA update
__device__ __forceinline__ void fma38(float acc[3][8], float a0, float a1, float a2,
                                      float4 b0, float4 b1) {
    float bb[8] = {b0.x, b0.y, b0.z, b0.w, b1.x, b1.y, b1.z, b1.w};
#pragma unroll
    for (int n = 0; n < 8; n++) {
        acc[0][n] = fmaf(a0, bb[n], acc[0][n]);
        acc[1][n] = fmaf(a1, bb[n], acc[1][n]);
        acc[2][n] = fmaf(a2, bb[n], acc[2][n]);
    }
}

// ---------------------------------------------------------------------------
// Kernel 1: per-sequence fused pipeline up to "last" context vector.
// grid = 32768 blocks, 128 threads.
// Thread grid for GEMM stages: 16 row-groups (3 rows each) x 8 col-groups (8 cols).
// ---------------------------------------------------------------------------
__global__ void __launch_bounds__(128) seq_kernel(
    const float* __restrict__ x,
    const float* __restrict__ W_in,  const float* __restrict__ b_in,
    const float* __restrict__ W_conv,const float* __restrict__ b_conv,
    const float* __restrict__ Wq,    const float* __restrict__ bq,
    const float* __restrict__ Wk,    const float* __restrict__ bk,
    const float* __restrict__ Wv,    const float* __restrict__ bv)
{
    __shared__ float sm[11072];
    float* h0p  = sm;            // [50][64], rows shifted by +1 (rows 0,49 = zero pad)
    float* xs   = sm + 3200;     // [48][32]
    float* hcs  = sm + 4736;     // [48][64] post-conv relu
    float* kbuf = sm;            // [48][64] (aliases h0p, safe after conv stage)
    float* vbuf = sm + 7808;     // [48][64]
    float* qs   = sm + 10880;    // [64]
    float* sc   = sm + 10944;    // [48] scores -> exp weights
    float* red  = sm + 10992;    // [1] softmax denom

    const int tid = threadIdx.x;
    const int seq = blockIdx.x;
    const int r3 = (tid >> 3) * 3;    // first of 3 rows
    const int j8 = (tid & 7) * 8;     // first of 8 cols

    // ---- load x (contiguous 1536 floats per sequence) ----
    const float* xg = x + (size_t)seq * (TT * EE);
#pragma unroll
    for (int i = 0; i < TT * EE / 128; i++)
        xs[tid + i * 128] = xg[tid + i * 128];
    if (tid < 64) { h0p[tid] = 0.f; h0p[49 * 64 + tid] = 0.f; }
    __syncthreads();

    // ---- stage 1: h0 = x @ W_in + b_in  (48x64, K=32) ----
    {
        float acc[3][8];
#pragma unroll
        for (int m = 0; m < 3; m++)
#pragma unroll
            for (int n = 0; n < 8; n++) acc[m][n] = 0.f;

#pragma unroll 4
        for (int k = 0; k < EE; k++) {
            float a0 = xs[(r3 + 0) * EE + k];
            float a1 = xs[(r3 + 1) * EE + k];
            float a2 = xs[(r3 + 2) * EE + k];
            float4 b0 = ldg4(W_in + k * CC + j8);
            float4 b1 = ldg4(W_in + k * CC + j8 + 4);
            fma38(acc, a0, a1, a2, b0, b1);
        }
        float4 c0 = ldg4(b_in + j8), c1 = ldg4(b_in + j8 + 4);
        float bi[8] = {c0.x, c0.y, c0.z, c0.w, c1.x, c1.y, c1.z, c1.w};
#pragma unroll
        for (int m = 0; m < 3; m++)
#pragma unroll
            for (int n = 0; n < 8; n++)
                h0p[(r3 + m + 1) * CC + j8 + n] = acc[m][n] + bi[n];
    }
    __syncthreads();

    // ---- stage 2: conv1d(k=3, pad=1) + bias + relu  (48x64, K=192) ----
    {
        float acc[3][8];
#pragma unroll
        for (int m = 0; m < 3; m++)
#pragma unroll
            for (int n = 0; n < 8; n++) acc[m][n] = 0.f;

#pragma unroll
        for (int d = 0; d < 3; d++) {
            const float* Wd = W_conv + d * CC * CC;
#pragma unroll 4
            for (int c0 = 0; c0 < CC; c0++) {
                // input row t+d-1 -> h0p row t+d (shifted layout)
                float a0 = h0p[(r3 + 0 + d) * CC + c0];
                float a1 = h0p[(r3 + 1 + d) * CC + c0];
                float a2 = h0p[(r3 + 2 + d) * CC + c0];
                float4 b0 = ldg4(Wd + c0 * CC + j8);
                float4 b1 = ldg4(Wd + c0 * CC + j8 + 4);
                fma38(acc, a0, a1, a2, b0, b1);
            }
        }
        float4 c0 = ldg4(b_conv + j8), c1 = ldg4(b_conv + j8 + 4);
        float bi[8] = {c0.x, c0.y, c0.z, c0.w, c1.x, c1.y, c1.z, c1.w};
#pragma unroll
        for (int m = 0; m < 3; m++)
#pragma unroll
            for (int n = 0; n < 8; n++)
                hcs[(r3 + m) * CC + j8 + n] = fmaxf(acc[m][n] + bi[n], 0.f);
    }
    __syncthreads();

    // ---- stage 3: K = hcs @ Wk + bk  (48x64, K=64) ---- (overwrites h0p region)
    {
        float acc[3][8];
#pragma unroll
        for (int m = 0; m < 3; m++)
#pragma unroll
            for (int n = 0; n < 8; n++) acc[m][n] = 0.f;
#pragma unroll 4
        for (int k = 0; k < CC; k++) {
            float a0 = hcs[(r3 + 0) * CC + k];
            float a1 = hcs[(r3 + 1) * CC + k];
            float a2 = hcs[(r3 + 2) * CC + k];
            float4 b0 = ldg4(Wk + k * CC + j8);
            float4 b1 = ldg4(Wk + k * CC + j8 + 4);
            fma38(acc, a0, a1, a2, b0, b1);
        }
        float4 c0 = ldg4(bk + j8), c1 = ldg4(bk + j8 + 4);
        float bi[8] = {c0.x, c0.y, c0.z, c0.w, c1.x, c1.y, c1.z, c1.w};
#pragma unroll
        for (int m = 0; m < 3; m++)
#pragma unroll
            for (int n = 0; n < 8; n++)
                kbuf[(r3 + m) * CC + j8 + n] = acc[m][n] + bi[n];
    }
    // no sync needed between K and V stages (disjoint outputs, hcs read-only)

    // ---- stage 4: V = hcs @ Wv + bv ----
    {
        float acc[3][8];
#pragma unroll
        for (int m = 0; m < 3; m++)
#pragma unroll
            for (int n = 0; n < 8; n++) acc[m][n] = 0.f;
#pragma unroll 4
        for (int k = 0; k < CC; k++) {
            float a0 = hcs[(r3 + 0) * CC + k];
            float a1 = hcs[(r3 + 1) * CC + k];
            float a2 = hcs[(r3 + 2) * CC + k];
            float4 b0 = ldg4(Wv + k * CC + j8);
            float4 b1 = ldg4(Wv + k * CC + j8 + 4);
            fma38(acc, a0, a1, a2, b0, b1);
        }
        float4 c0 = ldg4(bv + j8), c1 = ldg4(bv + j8 + 4);
        float bi[8] = {c0.x, c0.y, c0.z, c0.w, c1.x, c1.y, c1.z, c1.w};
#pragma unroll
        for (int m = 0; m < 3; m++)
#pragma unroll
            for (int n = 0; n < 8; n++)
                vbuf[(r3 + m) * CC + j8 + n] = acc[m][n] + bi[n];
    }

    // ---- stage 5: q only for t = 47 ----
    if (tid < CC) {
        float a = __ldg(bq + tid);
#pragma unroll 4
        for (int c0 = 0; c0 < CC; c0++)
            a = fmaf(hcs[47 * CC + c0], __ldg(Wq + c0 * CC + tid), a);
        qs[tid] = a;
    }
    __syncthreads();

    // ---- stage 6: scores[s] = q . k[s] / 8 (warp-reduced dots) ----
    {
        const int warp = tid >> 5, lane = tid & 31;
        for (int s = warp; s < TT; s += 4) {
            float p = qs[lane] * kbuf[s * CC + lane]
                    + qs[lane + 32] * kbuf[s * CC + lane + 32];
#pragma unroll
            for (int off = 16; off > 0; off >>= 1)
                p += __shfl_xor_sync(0xffffffffu, p, off);
            if (lane == 0) sc[s] = p * 0.125f;
        }
    }
    __syncthreads();

    // ---- stage 7: softmax weights (warp 0) ----
    if (tid < 32) {
        const int lane = tid;
        float v1 = sc[lane];
        float v2 = (lane < 16) ? sc[32 + lane] : -3.4e38f;
        float m = fmaxf(v1, v2);
#pragma unroll
        for (int off = 16; off > 0; off >>= 1)
            m = fmaxf(m, __shfl_xor_sync(0xffffffffu, m, off));
        float e1 = __expf(v1 - m);
        float e2 = (lane < 16) ? __expf(v2 - m) : 0.f;
        float ssum = e1 + e2;
#pragma unroll
        for (int off = 16; off > 0; off >>= 1)
            ssum += __shfl_xor_sync(0xffffffffu, ssum, off);
        sc[lane] = e1;
        if (lane < 16) sc[32 + lane] = e2;
        if (lane == 0) red[0] = ssum;
    }
    __syncthreads();

    // ---- stage 8: ctx (last row) = sum_s w[s] * v[s] / sum ----
    if (tid < CC) {
        float a = 0.f;
#pragma unroll 4
        for (int s = 0; s < TT; s++)
            a = fmaf(sc[s], vbuf[s * CC + tid], a);
        g_last[(size_t)seq * CC + tid] = a / red[0];
    }
}

// ---------------------------------------------------------------------------
// Kernel 2: batched MLP  last(64) -> relu 256 -> relu 128 -> 12, + transpose out.
// One warp per 4-row batch. grid = 2048 blocks x 128 threads -> 8192 warps.
// ---------------------------------------------------------------------------
__global__ void __launch_bounds__(128) mlp_kernel(
    const float* __restrict__ W1, const float* __restrict__ b1,
    const float* __restrict__ W2, const float* __restrict__ b2,
    const float* __restrict__ W3, const float* __restrict__ b3,
    float* __restrict__ out)
{
    __shared__ float sm[4 * 1536];
    const int warp = threadIdx.x >> 5, lane = threadIdx.x & 31;
    float* z1s = sm + warp * 1536;        // [4][256]
    float* z2s = z1s + 1024;              // [4][128]

    const int batch = blockIdx.x * 4 + warp;   // 0..8191
    const int row0 = batch * 4;

    // per-lane copies of the 4 input rows (64 each, split lane / lane+32)
    float al0[4], al1[4];
#pragma unroll
    for (int r = 0; r < 4; r++) {
        al0[r] = g_last[(size_t)(row0 + r) * CC + lane];
        al1[r] = g_last[(size_t)(row0 + r) * CC + 32 + lane];
    }

    // ---- layer 1: 64 -> 256 ----
    {
        float acc[4][8];
#pragma unroll
        for (int jj = 0; jj < 8; jj++) {
            float bb = __ldg(b1 + lane + 32 * jj);
#pragma unroll
            for (int r = 0; r < 4; r++) acc[r][jj] = bb;
        }
#pragma unroll 4
        for (int k = 0; k < 32; k++) {
            float w[8];
#pragma unroll
            for (int jj = 0; jj < 8; jj++) w[jj] = __ldg(W1 + k * H1 + lane + 32 * jj);
            float av[4];
#pragma unroll
            for (int r = 0; r < 4; r++) av[r] = __shfl_sync(0xffffffffu, al0[r], k);
#pragma unroll
            for (int r = 0; r < 4; r++)
#pragma unroll
                for (int jj = 0; jj < 8; jj++) acc[r][jj] = fmaf(av[r], w[jj], acc[r][jj]);
        }
#pragma unroll 4
        for (int k = 0; k < 32; k++) {
            float w[8];
#pragma unroll
            for (int jj = 0; jj < 8; jj++) w[jj] = __ldg(W1 + (k + 32) * H1 + lane + 32 * jj);
            float av[4];
#pragma unroll
            for (int r = 0; r < 4; r++) av[r] = __shfl_sync(0xffffffffu, al1[r], k);
#pragma unroll
            for (int r = 0; r < 4; r++)
#pragma unroll
                for (int jj = 0; jj < 8; jj++) acc[r][jj] = fmaf(av[r], w[jj], acc[r][jj]);
        }
#pragma unroll
        for (int r = 0; r < 4; r++)
#pragma unroll
            for (int jj = 0; jj < 8; jj++)
                z1s[r * H1 + lane + 32 * jj] = fmaxf(acc[r][jj], 0.f);
        __syncwarp();
    }

    // ---- layer 2: 256 -> 128 ----
    {
        float acc[4][4];
#pragma unroll
        for (int jj = 0; jj < 4; jj++) {
            float bb = __ldg(b2 + lane + 32 * jj);
#pragma unroll
            for (int r = 0; r < 4; r++) acc[r][jj] = bb;
        }
#pragma unroll 4
        for (int k = 0; k < H1; k++) {
            float w[4];
#pragma unroll
            for (int jj = 0; jj < 4; jj++) w[jj] = __ldg(W2 + k * H2 + lane + 32 * jj);
            float zv[4];
#pragma unroll
            for (int r = 0; r < 4; r++) zv[r] = z1s[r * H1 + k];
#pragma unroll
            for (int r = 0; r < 4; r++)
#pragma unroll
                for (int jj = 0; jj < 4; jj++) acc[r][jj] = fmaf(zv[r], w[jj], acc[r][jj]);
        }
#pragma unroll
        for (int r = 0; r < 4; r++)
#pragma unroll
            for (int jj = 0; jj < 4; jj++)
                z2s[r * H2 + lane + 32 * jj] = fmaxf(acc[r][jj], 0.f);
        __syncwarp();
    }

    // ---- layer 3: 128 -> 12, write transposed output ----
#pragma unroll
    for (int r = 0; r < 4; r++) {
        if (lane < NPRED) {
            float a = __ldg(b3 + lane);
#pragma unroll 4
            for (int k = 0; k < H2; k++)
                a = fmaf(z2s[r * H2 + k], __ldg(W3 + k * NPRED + lane), a);
            const int row = row0 + r;
            const int b = row >> 11;          // / 2048
            const int n = row & 2047;
            out[(size_t)b * (NPRED * NN) + (size_t)lane * NN + n] = a;
        }
    }
}

// ---------------------------------------------------------------------------
extern "C" void kernel_launch(void* const* d_in, const int* in_sizes, int n_in,
                              void* d_out, int out_size) {
    const float* x      = (const float*)d_in[0];
    const float* W_in   = (const float*)d_in[1];
    const float* b_in   = (const float*)d_in[2];
    const float* W_conv = (const float*)d_in[3];
    const float* b_conv = (const float*)d_in[4];
    const float* Wq     = (const float*)d_in[5];
    const float* bq     = (const float*)d_in[6];
    const float* Wk     = (const float*)d_in[7];
    const float* bk     = (const float*)d_in[8];
    const float* Wv     = (const float*)d_in[9];
    const float* bv     = (const float*)d_in[10];
    const float* W1     = (const float*)d_in[11];
    const float* b1     = (const float*)d_in[12];
    const float* W2     = (const float*)d_in[13];
    const float* b2     = (const float*)d_in[14];
    const float* W3     = (const float*)d_in[15];
    const float* b3     = (const float*)d_in[16];
    float* out = (float*)d_out;

    seq_kernel<<<NSEQ, 128>>>(x, W_in, b_in, W_conv, b_conv,
                              Wq, bq, Wk, bk, Wv, bv);
    mlp_kernel<<<NSEQ / 16, 128>>>(W1, b1, W2, b2, W3, b3, out);
}

// round 3
// speedup vs baseline: 4.1341x; 4.1341x over previous
#include <cuda_runtime.h>
#include <cuda_bf16.h>

// ---------------- problem constants ----------------
#define BB   16
#define NN   2048
#define NSEQ (BB*NN)      // 32768
#define TT   48
#define EE   32
#define CC   64
#define H1   256
#define H2   128
#define NPRED 12

// scratch
__device__ float g_last[NSEQ * CC];
// pre-swizzled weight B-fragments (hi/lo bf16 pairs), 22 ksteps x 8 nblocks x 32 lanes
__device__ uint2 g_Bh2[22 * 8 * 32];
__device__ uint2 g_Bl2[22 * 8 * 32];

// ---------------- helpers ----------------
__device__ __forceinline__ unsigned short f2bf(float f) {
    __nv_bfloat16 h = __float2bfloat16(f);
    return *reinterpret_cast<unsigned short*>(&h);
}
__device__ __forceinline__ float bf2f(unsigned short u) {
    __nv_bfloat16 h = *reinterpret_cast<__nv_bfloat16*>(&u);
    return __bfloat162float(h);
}
__device__ __forceinline__ unsigned scvta(const void* p) {
    return (unsigned)__cvta_generic_to_shared(p);
}
__device__ __forceinline__ void ldsm4(unsigned a[4], unsigned saddr) {
    asm volatile("ldmatrix.sync.aligned.m8n8.x4.shared.b16 {%0,%1,%2,%3},[%4];"
                 : "=r"(a[0]), "=r"(a[1]), "=r"(a[2]), "=r"(a[3]) : "r"(saddr));
}
__device__ __forceinline__ void mma_bf16(float* c, const unsigned a[4], uint2 b) {
    asm volatile(
        "mma.sync.aligned.m16n8k16.row.col.f32.bf16.bf16.f32 "
        "{%0,%1,%2,%3},{%4,%5,%6,%7},{%8,%9},{%0,%1,%2,%3};"
        : "+f"(c[0]), "+f"(c[1]), "+f"(c[2]), "+f"(c[3])
        : "r"(a[0]), "r"(a[1]), "r"(a[2]), "r"(a[3]), "r"(b.x), "r"(b.y));
}
__device__ __forceinline__ void st_split(unsigned short* H, unsigned short* L, int idx, float v) {
    unsigned short h = f2bf(v);
    H[idx] = h;
    L[idx] = f2bf(v - bf2f(h));
}

// ---------------------------------------------------------------------------
// prep: split weights into bf16 hi/lo and pre-swizzle into mma B-fragment order.
// global kstep map: [0,2) W_in | [2,14) W_conv taps 0..2 | [14,18) Wk | [18,22) Wv
// ---------------------------------------------------------------------------
__global__ void prep_kernel(const float* __restrict__ W_in,
                            const float* __restrict__ W_conv,
                            const float* __restrict__ Wk,
                            const float* __restrict__ Wv)
{
    int e = blockIdx.x * 256 + threadIdx.x;
    if (e >= 22 * 8 * 32) return;
    int lane = e & 31;
    int nb   = (e >> 5) & 7;
    int ks   = e >> 8;

    const float* W;
    int kb;
    if (ks < 2)       { W = W_in;                          kb = ks * 16; }
    else if (ks < 14) { int t = ks - 2; W = W_conv + (t >> 2) * (CC * CC); kb = (t & 3) * 16; }
    else if (ks < 18) { W = Wk;                            kb = (ks - 14) * 16; }
    else              { W = Wv;                            kb = (ks - 18) * 16; }

    int n = nb * 8 + (lane >> 2);
    unsigned hi[2], lo[2];
#pragma unroll
    for (int r = 0; r < 2; r++) {
        int k = kb + (lane & 3) * 2 + r * 8;
        float w0 = W[k * CC + n];
        float w1 = W[(k + 1) * CC + n];
        unsigned short h0 = f2bf(w0), h1 = f2bf(w1);
        unsigned short l0 = f2bf(w0 - bf2f(h0)), l1 = f2bf(w1 - bf2f(h1));
        hi[r] = (unsigned)h0 | ((unsigned)h1 << 16);
        lo[r] = (unsigned)l0 | ((unsigned)l1 << 16);
    }
    int idx = (ks * 8 + nb) * 32 + lane;
    g_Bh2[idx] = make_uint2(hi[0], hi[1]);
    g_Bl2[idx] = make_uint2(lo[0], lo[1]);
}

// ---------------------------------------------------------------------------
// bf16x3 GEMM accumulate: 48x64 output tile, warp w owns cols [16w,16w+16).
// A from smem (hi/lo bf16, padded stride), B from pre-swizzled global.
// ---------------------------------------------------------------------------
__device__ __forceinline__ void gemm_acc(
    const unsigned short* __restrict__ Ah, const unsigned short* __restrict__ Al,
    int stride, int ks0, int nks, int rowoff,
    float acc[3][2][4], int lane, int warp)
{
    const int row_l = (lane & 7) | (((lane >> 3) & 1) << 3);
    const int col_l = (lane >> 4) << 3;

    for (int ks = 0; ks < nks; ks++) {
        int bidx = ((ks0 + ks) * 8 + 2 * warp) * 32 + lane;
        uint2 bh0 = __ldg(&g_Bh2[bidx]);
        uint2 bh1 = __ldg(&g_Bh2[bidx + 32]);
        uint2 bl0 = __ldg(&g_Bl2[bidx]);
        uint2 bl1 = __ldg(&g_Bl2[bidx + 32]);
#pragma unroll
        for (int mb = 0; mb < 3; mb++) {
            int aoff = (rowoff + mb * 16 + row_l) * stride + ks * 16 + col_l;
            unsigned ah[4], al[4];
            ldsm4(ah, scvta(Ah + aoff));
            ldsm4(al, scvta(Al + aoff));
            mma_bf16(acc[mb][0], ah, bh0);
            mma_bf16(acc[mb][0], ah, bl0);
            mma_bf16(acc[mb][0], al, bh0);
            mma_bf16(acc[mb][1], ah, bh1);
            mma_bf16(acc[mb][1], ah, bl1);
            mma_bf16(acc[mb][1], al, bh1);
        }
    }
}

__device__ __forceinline__ void zero_acc(float acc[3][2][4]) {
#pragma unroll
    for (int m = 0; m < 3; m++)
#pragma unroll
        for (int n = 0; n < 2; n++)
#pragma unroll
            for (int i = 0; i < 4; i++) acc[m][n][i] = 0.f;
}

// ---------------------------------------------------------------------------
// Kernel 1: per-sequence fused pipeline (tensor-core GEMM stages)
// ---------------------------------------------------------------------------
__global__ void __launch_bounds__(128) seq_kernel(
    const float* __restrict__ x,
    const float* __restrict__ b_in, const float* __restrict__ b_conv,
    const float* __restrict__ Wq,   const float* __restrict__ bq,
    const float* __restrict__ bk,   const float* __restrict__ bv)
{
    __shared__ __align__(16) unsigned char smraw[39168];
    float*          kbuf = (float*)smraw;                     // [48][64] (aliases xh/xl/h0h head)
    float*          vbuf = (float*)(smraw + 12288);           // [48][64] (aliases h0h tail/h0l)
    unsigned short* xh   = (unsigned short*)smraw;            // [48][40]
    unsigned short* xl   = (unsigned short*)(smraw + 3840);
    unsigned short* h0h  = (unsigned short*)(smraw + 7680);   // [50][72] (rows shifted +1; rows 0,49 zero)
    unsigned short* h0l  = (unsigned short*)(smraw + 14880);
    unsigned short* hch  = (unsigned short*)(smraw + 24576);  // [48][72]
    unsigned short* hcl  = (unsigned short*)(smraw + 31488);
    float*          r47  = (float*)(smraw + 38400);           // [64] fp32 conv row 47
    float*          qs   = (float*)(smraw + 38656);           // [64]
    float*          sc   = (float*)(smraw + 38912);           // [48]
    float*          red  = (float*)(smraw + 39104);           // [1]

    const int tid  = threadIdx.x;
    const int lane = tid & 31;
    const int warp = tid >> 5;
    const int seq  = blockIdx.x;

    // ---- load + split x ----
    const float* xg = x + (size_t)seq * (TT * EE);
#pragma unroll
    for (int i = tid; i < TT * EE; i += 128) {
        int row = i >> 5, col = i & 31;
        float v = xg[i];
        unsigned short h = f2bf(v);
        xh[row * 40 + col] = h;
        xl[row * 40 + col] = f2bf(v - bf2f(h));
    }
    if (tid < 64) {
        h0h[tid] = 0; h0l[tid] = 0;
        h0h[49 * 72 + tid] = 0; h0l[49 * 72 + tid] = 0;
    }
    __syncthreads();

    const int R  = lane >> 2;
    const int Cb = warp * 16;
    float acc[3][2][4];

    // ---- stage 1: h0 = x @ W_in + b_in ----
    zero_acc(acc);
    gemm_acc(xh, xl, 40, 0, 2, 0, acc, lane, warp);
#pragma unroll
    for (int nb = 0; nb < 2; nb++) {
        int C0 = Cb + nb * 8 + (lane & 3) * 2;
        float bi0 = b_in[C0], bi1 = b_in[C0 + 1];
#pragma unroll
        for (int mb = 0; mb < 3; mb++) {
            int r0 = mb * 16 + R, r1 = r0 + 8;
            st_split(h0h, h0l, (r0 + 1) * 72 + C0,     acc[mb][nb][0] + bi0);
            st_split(h0h, h0l, (r0 + 1) * 72 + C0 + 1, acc[mb][nb][1] + bi1);
            st_split(h0h, h0l, (r1 + 1) * 72 + C0,     acc[mb][nb][2] + bi0);
            st_split(h0h, h0l, (r1 + 1) * 72 + C0 + 1, acc[mb][nb][3] + bi1);
        }
    }
    __syncthreads();

    // ---- stage 2: conv1d(k=3,pad=1) + bias + relu ----
    zero_acc(acc);
#pragma unroll
    for (int d = 0; d < 3; d++)
        gemm_acc(h0h, h0l, 72, 2 + 4 * d, 4, d, acc, lane, warp);
#pragma unroll
    for (int nb = 0; nb < 2; nb++) {
        int C0 = Cb + nb * 8 + (lane & 3) * 2;
        float bi0 = b_conv[C0], bi1 = b_conv[C0 + 1];
#pragma unroll
        for (int mb = 0; mb < 3; mb++) {
            int r0 = mb * 16 + R, r1 = r0 + 8;
            float v0 = fmaxf(acc[mb][nb][0] + bi0, 0.f);
            float v1 = fmaxf(acc[mb][nb][1] + bi1, 0.f);
            float v2 = fmaxf(acc[mb][nb][2] + bi0, 0.f);
            float v3 = fmaxf(acc[mb][nb][3] + bi1, 0.f);
            st_split(hch, hcl, r0 * 72 + C0,     v0);
            st_split(hch, hcl, r0 * 72 + C0 + 1, v1);
            st_split(hch, hcl, r1 * 72 + C0,     v2);
            st_split(hch, hcl, r1 * 72 + C0 + 1, v3);
            if (r1 == 47) { r47[C0] = v2; r47[C0 + 1] = v3; }
        }
    }
    __syncthreads();

    // ---- stage 3: K = hcs @ Wk + bk ----
    zero_acc(acc);
    gemm_acc(hch, hcl, 72, 14, 4, 0, acc, lane, warp);
#pragma unroll
    for (int nb = 0; nb < 2; nb++) {
        int C0 = Cb + nb * 8 + (lane & 3) * 2;
        float bi0 = bk[C0], bi1 = bk[C0 + 1];
#pragma unroll
        for (int mb = 0; mb < 3; mb++) {
            int r0 = mb * 16 + R, r1 = r0 + 8;
            kbuf[r0 * 64 + C0]     = acc[mb][nb][0] + bi0;
            kbuf[r0 * 64 + C0 + 1] = acc[mb][nb][1] + bi1;
            kbuf[r1 * 64 + C0]     = acc[mb][nb][2] + bi0;
            kbuf[r1 * 64 + C0 + 1] = acc[mb][nb][3] + bi1;
        }
    }

    // ---- stage 4: V = hcs @ Wv + bv ----
    zero_acc(acc);
    gemm_acc(hch, hcl, 72, 18, 4, 0, acc, lane, warp);
#pragma unroll
    for (int nb = 0; nb < 2; nb++) {
        int C0 = Cb + nb * 8 + (lane & 3) * 2;
        float bi0 = bv[C0], bi1 = bv[C0 + 1];
#pragma unroll
        for (int mb = 0; mb < 3; mb++) {
            int r0 = mb * 16 + R, r1 = r0 + 8;
            vbuf[r0 * 64 + C0]     = acc[mb][nb][0] + bi0;
            vbuf[r0 * 64 + C0 + 1] = acc[mb][nb][1] + bi1;
            vbuf[r1 * 64 + C0]     = acc[mb][nb][2] + bi0;
            vbuf[r1 * 64 + C0 + 1] = acc[mb][nb][3] + bi1;
        }
    }

    // ---- q for t = 47 (scalar fp32) ----
    if (tid < CC) {
        float a = __ldg(bq + tid);
#pragma unroll 4
        for (int c0 = 0; c0 < CC; c0++)
            a = fmaf(r47[c0], __ldg(Wq + c0 * CC + tid), a);
        qs[tid] = a;
    }
    __syncthreads();

    // ---- scores ----
    for (int s = warp; s < TT; s += 4) {
        float p = qs[lane] * kbuf[s * CC + lane]
                + qs[lane + 32] * kbuf[s * CC + lane + 32];
#pragma unroll
        for (int off = 16; off > 0; off >>= 1)
            p += __shfl_xor_sync(0xffffffffu, p, off);
        if (lane == 0) sc[s] = p * 0.125f;
    }
    __syncthreads();

    // ---- softmax weights (warp 0) ----
    if (tid < 32) {
        float v1 = sc[tid];
        float v2 = (tid < 16) ? sc[32 + tid] : -3.4e38f;
        float m = fmaxf(v1, v2);
#pragma unroll
        for (int off = 16; off > 0; off >>= 1)
            m = fmaxf(m, __shfl_xor_sync(0xffffffffu, m, off));
        float e1 = __expf(v1 - m);
        float e2 = (tid < 16) ? __expf(v2 - m) : 0.f;
        float ssum = e1 + e2;
#pragma unroll
        for (int off = 16; off > 0; off >>= 1)
            ssum += __shfl_xor_sync(0xffffffffu, ssum, off);
        sc[tid] = e1;
        if (tid < 16) sc[32 + tid] = e2;
        if (tid == 0) red[0] = ssum;
    }
    __syncthreads();

    // ---- ctx (last row) ----
    if (tid < CC) {
        float a = 0.f;
#pragma unroll 4
        for (int s = 0; s < TT; s++)
            a = fmaf(sc[s], vbuf[s * CC + tid], a);
        g_last[(size_t)seq * CC + tid] = a / red[0];
    }
}

// ---------------------------------------------------------------------------
// Kernel 2: batched MLP
// ---------------------------------------------------------------------------
__global__ void __launch_bounds__(128) mlp_kernel(
    const float* __restrict__ W1, const float* __restrict__ b1,
    const float* __restrict__ W2, const float* __restrict__ b2,
    const float* __restrict__ W3, const float* __restrict__ b3,
    float* __restrict__ out)
{
    __shared__ float sm[4 * 1536];
    const int warp = threadIdx.x >> 5, lane = threadIdx.x & 31;
    float* z1s = sm + warp * 1536;
    float* z2s = z1s + 1024;

    const int batch = blockIdx.x * 4 + warp;
    const int row0 = batch * 4;

    float al0[4], al1[4];
#pragma unroll
    for (int r = 0; r < 4; r++) {
        al0[r] = g_last[(size_t)(row0 + r) * CC + lane];
        al1[r] = g_last[(size_t)(row0 + r) * CC + 32 + lane];
    }

    {
        float acc[4][8];
#pragma unroll
        for (int jj = 0; jj < 8; jj++) {
            float bb = __ldg(b1 + lane + 32 * jj);
#pragma unroll
            for (int r = 0; r < 4; r++) acc[r][jj] = bb;
        }
#pragma unroll 4
        for (int k = 0; k < 32; k++) {
            float w[8];
#pragma unroll
            for (int jj = 0; jj < 8; jj++) w[jj] = __ldg(W1 + k * H1 + lane + 32 * jj);
            float av[4];
#pragma unroll
            for (int r = 0; r < 4; r++) av[r] = __shfl_sync(0xffffffffu, al0[r], k);
#pragma unroll
            for (int r = 0; r < 4; r++)
#pragma unroll
                for (int jj = 0; jj < 8; jj++) acc[r][jj] = fmaf(av[r], w[jj], acc[r][jj]);
        }
#pragma unroll 4
        for (int k = 0; k < 32; k++) {
            float w[8];
#pragma unroll
            for (int jj = 0; jj < 8; jj++) w[jj] = __ldg(W1 + (k + 32) * H1 + lane + 32 * jj);
            float av[4];
#pragma unroll
            for (int r = 0; r < 4; r++) av[r] = __shfl_sync(0xffffffffu, al1[r], k);
#pragma unroll
            for (int r = 0; r < 4; r++)
#pragma unroll
                for (int jj = 0; jj < 8; jj++) acc[r][jj] = fmaf(av[r], w[jj], acc[r][jj]);
        }
#pragma unroll
        for (int r = 0; r < 4; r++)
#pragma unroll
            for (int jj = 0; jj < 8; jj++)
                z1s[r * H1 + lane + 32 * jj] = fmaxf(acc[r][jj], 0.f);
        __syncwarp();
    }

    {
        float acc[4][4];
#pragma unroll
        for (int jj = 0; jj < 4; jj++) {
            float bb = __ldg(b2 + lane + 32 * jj);
#pragma unroll
            for (int r = 0; r < 4; r++) acc[r][jj] = bb;
        }
#pragma unroll 4
        for (int k = 0; k < H1; k++) {
            float w[4];
#pragma unroll
            for (int jj = 0; jj < 4; jj++) w[jj] = __ldg(W2 + k * H2 + lane + 32 * jj);
            float zv[4];
#pragma unroll
            for (int r = 0; r < 4; r++) zv[r] = z1s[r * H1 + k];
#pragma unroll
            for (int r = 0; r < 4; r++)
#pragma unroll
                for (int jj = 0; jj < 4; jj++) acc[r][jj] = fmaf(zv[r], w[jj], acc[r][jj]);
        }
#pragma unroll
        for (int r = 0; r < 4; r++)
#pragma unroll
            for (int jj = 0; jj < 4; jj++)
                z2s[r * H2 + lane + 32 * jj] = fmaxf(acc[r][jj], 0.f);
        __syncwarp();
    }

#pragma unroll
    for (int r = 0; r < 4; r++) {
        if (lane < NPRED) {
            float a = __ldg(b3 + lane);
#pragma unroll 4
            for (int k = 0; k < H2; k++)
                a = fmaf(z2s[r * H2 + k], __ldg(W3 + k * NPRED + lane), a);
            const int row = row0 + r;
            const int b = row >> 11;
            const int n = row & 2047;
            out[(size_t)b * (NPRED * NN) + (size_t)lane * NN + n] = a;
        }
    }
}

// ---------------------------------------------------------------------------
extern "C" void kernel_launch(void* const* d_in, const int* in_sizes, int n_in,
                              void* d_out, int out_size) {
    const float* x      = (const float*)d_in[0];
    const float* W_in   = (const float*)d_in[1];
    const float* b_in   = (const float*)d_in[2];
    const float* W_conv = (const float*)d_in[3];
    const float* b_conv = (const float*)d_in[4];
    const float* Wq     = (const float*)d_in[5];
    const float* bq     = (const float*)d_in[6];
    const float* Wk     = (const float*)d_in[7];
    const float* bk     = (const float*)d_in[8];
    const float* Wv     = (const float*)d_in[9];
    const float* bv     = (const float*)d_in[10];
    const float* W1     = (const float*)d_in[11];
    const float* b1     = (const float*)d_in[12];
    const float* W2     = (const float*)d_in[13];
    const float* b2     = (const float*)d_in[14];
    const float* W3     = (const float*)d_in[15];
    const float* b3     = (const float*)d_in[16];
    float* out = (float*)d_out;

    prep_kernel<<<22, 256>>>(W_in, W_conv, Wk, Wv);
    seq_kernel<<<NSEQ, 128>>>(x, b_in, b_conv, Wq, bq, bk, bv);
    mlp_kernel<<<NSEQ / 16, 128>>>(W1, b1, W2, b2, W3, b3, out);
}

// round 12
// speedup vs baseline: 6.3253x; 1.5300x over previous
#include <cuda_runtime.h>
#include <cuda_bf16.h>

// ---------------- problem constants ----------------
#define BB   16
#define NN   2048
#define NSEQ (BB*NN)      // 32768
#define TT   48
#define EE   32
#define CC   64
#define H1   256
#define H2   128
#define NPRED 12

// ---------------- device scratch ----------------
__device__ float g_last[NSEQ * CC];
// composite conv weights, pre-swizzled B-fragments (hi/lo bf16): 6 ksteps x 8 nb x 32 lanes
__device__ uint2 g_Bh2[6 * 8 * 32];
__device__ uint2 g_Bl2[6 * 8 * 32];
__device__ float g_bias[3 * CC];    // [0]=t0, [1]=interior, [2]=t47
__device__ float g_M[CC * CC];      // M[e][c] = sum_j Wq[e,j] Wk[c,j]
__device__ float g_vkb[CC];         // Wk . bq
__device__ float g_wqbk[CC];        // Wq . bk
__device__ float g_bqbk[1];         // bq . bk

// ---------------- helpers ----------------
__device__ __forceinline__ unsigned short f2bf(float f) {
    __nv_bfloat16 h = __float2bfloat16(f);
    return *reinterpret_cast<unsigned short*>(&h);
}
__device__ __forceinline__ float bf2f(unsigned short u) {
    __nv_bfloat16 h = *reinterpret_cast<__nv_bfloat16*>(&u);
    return __bfloat162float(h);
}
__device__ __forceinline__ unsigned scvta(const void* p) {
    return (unsigned)__cvta_generic_to_shared(p);
}
__device__ __forceinline__ void ldsm4(unsigned a[4], unsigned saddr) {
    asm volatile("ldmatrix.sync.aligned.m8n8.x4.shared.b16 {%0,%1,%2,%3},[%4];"
                 : "=r"(a[0]), "=r"(a[1]), "=r"(a[2]), "=r"(a[3]) : "r"(saddr));
}
__device__ __forceinline__ void mma_bf16(float* c, const unsigned a[4], uint2 b) {
    asm volatile(
        "mma.sync.aligned.m16n8k16.row.col.f32.bf16.bf16.f32 "
        "{%0,%1,%2,%3},{%4,%5,%6,%7},{%8,%9},{%0,%1,%2,%3};"
        : "+f"(c[0]), "+f"(c[1]), "+f"(c[2]), "+f"(c[3])
        : "r"(a[0]), "r"(a[1]), "r"(a[2]), "r"(a[3]), "r"(b.x), "r"(b.y));
}

// ---------------------------------------------------------------------------
// prep: build composite conv weights Wcomp[d] = W_in @ W_conv[d] (fp32),
// split hi/lo bf16, swizzle to mma B-frag order; plus bias vectors and the
// attention-folding matrices (all exact fp32).
// index map: [0,1536) conv frags | [1536,1728) bias | [1728,5824) M |
//            [5824,5888) vkb | [5888,5952) wqbk | [5952] bqbk
// ---------------------------------------------------------------------------
__global__ void prep_kernel(const float* __restrict__ W_in,
                            const float* __restrict__ W_conv,
                            const float* __restrict__ b_in,
                            const float* __restrict__ b_conv,
                            const float* __restrict__ Wq,
                            const float* __restrict__ bq,
                            const float* __restrict__ Wk,
                            const float* __restrict__ bk)
{
    int idx = blockIdx.x * 256 + threadIdx.x;

    if (idx < 1536) {
        int lane = idx & 31;
        int nb   = (idx >> 5) & 7;
        int ks   = idx >> 8;          // 0..5
        int d    = ks >> 1;
        int kb   = (ks & 1) * 16;
        int n    = nb * 8 + (lane >> 2);
        const float* Wc = W_conv + d * (CC * CC);

        unsigned hi[2], lo[2];
#pragma unroll
        for (int r = 0; r < 2; r++) {
            int k = kb + (lane & 3) * 2 + r * 8;
            float w0 = 0.f, w1 = 0.f;
#pragma unroll 4
            for (int c = 0; c < CC; c++) {
                float wc = Wc[c * CC + n];
                w0 = fmaf(W_in[k * CC + c], wc, w0);
                w1 = fmaf(W_in[(k + 1) * CC + c], wc, w1);
            }
            unsigned short h0 = f2bf(w0), h1 = f2bf(w1);
            unsigned short l0 = f2bf(w0 - bf2f(h0)), l1 = f2bf(w1 - bf2f(h1));
            hi[r] = (unsigned)h0 | ((unsigned)h1 << 16);
            lo[r] = (unsigned)l0 | ((unsigned)l1 << 16);
        }
        int o = (ks * 8 + nb) * 32 + lane;
        g_Bh2[o] = make_uint2(hi[0], hi[1]);
        g_Bl2[o] = make_uint2(lo[0], lo[1]);
    }
    else if (idx < 1728) {
        int i = idx - 1536;
        int which = i >> 6;           // 0=t0, 1=mid, 2=t47
        int n = i & 63;
        float s0 = 0.f, s1 = 0.f, s2 = 0.f;
#pragma unroll 4
        for (int c = 0; c < CC; c++) {
            float bc = b_in[c];
            s0 = fmaf(bc, W_conv[(0 * CC + c) * CC + n], s0);
            s1 = fmaf(bc, W_conv[(1 * CC + c) * CC + n], s1);
            s2 = fmaf(bc, W_conv[(2 * CC + c) * CC + n], s2);
        }
        float v = b_conv[n];
        if (which == 0)      v += s1 + s2;       // t=0: tap 0 missing
        else if (which == 1) v += s0 + s1 + s2;  // interior
        else                 v += s0 + s1;       // t=47: tap 2 missing
        g_bias[which * CC + n] = v;
    }
    else if (idx < 5824) {
        int i = idx - 1728;
        int e = i >> 6, c = i & 63;
        float a = 0.f;
#pragma unroll 4
        for (int j = 0; j < CC; j++)
            a = fmaf(Wq[e * CC + j], Wk[c * CC + j], a);
        g_M[e * CC + c] = a;
    }
    else if (idx < 5888) {
        int c = idx - 5824;
        float a = 0.f;
#pragma unroll 4
        for (int j = 0; j < CC; j++)
            a = fmaf(Wk[c * CC + j], bq[j], a);
        g_vkb[c] = a;
    }
    else if (idx < 5952) {
        int e = idx - 5888;
        float a = 0.f;
#pragma unroll 4
        for (int j = 0; j < CC; j++)
            a = fmaf(Wq[e * CC + j], bk[j], a);
        g_wqbk[e] = a;
    }
    else if (idx == 5952) {
        float a = 0.f;
#pragma unroll 4
        for (int j = 0; j < CC; j++)
            a = fmaf(bq[j], bk[j], a);
        g_bqbk[0] = a;
    }
}

// ---------------------------------------------------------------------------
// Kernel 1: per-sequence fused pipeline.
// conv output hc = relu(x (*) Wcomp + bias) via bf16x3 mma (108 HMMA/warp),
// then algebraic attention (u-vector trick) + weighted-V fold, all scalar fp32.
// ---------------------------------------------------------------------------
__global__ void __launch_bounds__(128) seq_kernel(
    const float* __restrict__ x,
    const float* __restrict__ Wv,
    const float* __restrict__ bv)
{
    __shared__ __align__(16) unsigned char smraw[21024];
    unsigned short* xh  = (unsigned short*)smraw;              // [50][40] (rows 0,49 zero)
    unsigned short* xl  = (unsigned short*)(smraw + 4000);     // [50][40]
    float*          hc  = (float*)(smraw + 8000);              // [48][64] fp32
    float*          us  = (float*)(smraw + 20288);             // [64]
    float*          ws  = (float*)(smraw + 20544);             // [64] wsum
    float*          sc  = (float*)(smraw + 20800);             // [48]
    float*          red = (float*)(smraw + 20992);             // [0]=denom [1]=qconst

    const int tid  = threadIdx.x;
    const int lane = tid & 31;
    const int warp = tid >> 5;
    const int seq  = blockIdx.x;

    // ---- load + split x into padded rows 1..48 ----
    const float* xg = x + (size_t)seq * (TT * EE);
#pragma unroll
    for (int i = tid; i < TT * EE; i += 128) {
        int row = (i >> 5) + 1, col = i & 31;
        float v = xg[i];
        unsigned short h = f2bf(v);
        xh[row * 40 + col] = h;
        xl[row * 40 + col] = f2bf(v - bf2f(h));
    }
    if (tid < 32) {
        xh[tid] = 0; xl[tid] = 0;
        xh[49 * 40 + tid] = 0; xl[49 * 40 + tid] = 0;
    }
    __syncthreads();

    // ---- fused conv GEMM: 48x64, 3 taps x K=32 (bf16x3) ----
    const int R     = lane >> 2;
    const int Cb    = warp * 16;
    const int row_l = (lane & 7) | (((lane >> 3) & 1) << 3);
    const int col_l = (lane >> 4) << 3;

    float acc[3][2][4];
#pragma unroll
    for (int m = 0; m < 3; m++)
#pragma unroll
        for (int n = 0; n < 2; n++)
#pragma unroll
            for (int i = 0; i < 4; i++) acc[m][n][i] = 0.f;

#pragma unroll
    for (int d = 0; d < 3; d++) {
#pragma unroll
        for (int ks = 0; ks < 2; ks++) {
            int bidx = ((d * 2 + ks) * 8 + 2 * warp) * 32 + lane;
            uint2 bh0 = __ldg(&g_Bh2[bidx]);
            uint2 bh1 = __ldg(&g_Bh2[bidx + 32]);
            uint2 bl0 = __ldg(&g_Bl2[bidx]);
            uint2 bl1 = __ldg(&g_Bl2[bidx + 32]);
#pragma unroll
            for (int mb = 0; mb < 3; mb++) {
                int aoff = (d + mb * 16 + row_l) * 40 + ks * 16 + col_l;
                unsigned ah[4], al[4];
                ldsm4(ah, scvta(xh + aoff));
                ldsm4(al, scvta(xl + aoff));
                mma_bf16(acc[mb][0], ah, bh0);
                mma_bf16(acc[mb][0], ah, bl0);
                mma_bf16(acc[mb][0], al, bh0);
                mma_bf16(acc[mb][1], ah, bh1);
                mma_bf16(acc[mb][1], ah, bl1);
                mma_bf16(acc[mb][1], al, bh1);
            }
        }
    }

    // ---- epilogue: bias + relu -> hc (fp32) ----
#pragma unroll
    for (int nb = 0; nb < 2; nb++) {
        int C0 = Cb + nb * 8 + (lane & 3) * 2;
#pragma unroll
        for (int mb = 0; mb < 3; mb++) {
            int r0 = mb * 16 + R, r1 = r0 + 8;
            const float* bp0 = g_bias + ((r0 == 0) ? 0 : CC);           // r0 never 47
            const float* bp1 = g_bias + ((r1 == 47) ? 2 * CC : CC);     // r1 never 0
            float2 v0, v1;
            v0.x = fmaxf(acc[mb][nb][0] + bp0[C0],     0.f);
            v0.y = fmaxf(acc[mb][nb][1] + bp0[C0 + 1], 0.f);
            v1.x = fmaxf(acc[mb][nb][2] + bp1[C0],     0.f);
            v1.y = fmaxf(acc[mb][nb][3] + bp1[C0 + 1], 0.f);
            *reinterpret_cast<float2*>(&hc[r0 * CC + C0]) = v0;
            *reinterpret_cast<float2*>(&hc[r1 * CC + C0]) = v1;
        }
    }
    __syncthreads();

    // ---- u = M^T hc47 + vkb  (tids 0..63); qconst (warp 2) ----
    if (tid < CC) {
        float a = g_vkb[tid];
#pragma unroll 4
        for (int e = 0; e < CC; e++)
            a = fmaf(hc[47 * CC + e], __ldg(&g_M[e * CC + tid]), a);
        us[tid] = a;
    } else if (warp == 2) {
        float p = hc[47 * CC + lane] * g_wqbk[lane]
                + hc[47 * CC + lane + 32] * g_wqbk[lane + 32];
#pragma unroll
        for (int off = 16; off > 0; off >>= 1)
            p += __shfl_xor_sync(0xffffffffu, p, off);
        if (lane == 0) red[1] = p + g_bqbk[0];
    }
    __syncthreads();

    // ---- scores_s = (hc_s . u + qconst) / 8 ----
    {
        float qc = red[1];
        for (int s = warp; s < TT; s += 4) {
            float p = us[lane] * hc[s * CC + lane]
                    + us[lane + 32] * hc[s * CC + lane + 32];
#pragma unroll
            for (int off = 16; off > 0; off >>= 1)
                p += __shfl_xor_sync(0xffffffffu, p, off);
            if (lane == 0) sc[s] = (p + qc) * 0.125f;
        }
    }
    __syncthreads();

    // ---- softmax weights (warp 0) ----
    if (tid < 32) {
        float v1 = sc[tid];
        float v2 = (tid < 16) ? sc[32 + tid] : -3.4e38f;
        float m = fmaxf(v1, v2);
#pragma unroll
        for (int off = 16; off > 0; off >>= 1)
            m = fmaxf(m, __shfl_xor_sync(0xffffffffu, m, off));
        float e1 = __expf(v1 - m);
        float e2 = (tid < 16) ? __expf(v2 - m) : 0.f;
        float ssum = e1 + e2;
#pragma unroll
        for (int off = 16; off > 0; off >>= 1)
            ssum += __shfl_xor_sync(0xffffffffu, ssum, off);
        sc[tid] = e1;
        if (tid < 16) sc[32 + tid] = e2;
        if (tid == 0) red[0] = ssum;
    }
    __syncthreads();

    // ---- wsum_c = sum_s e_s * hc[s][c] ----
    if (tid < CC) {
        float a = 0.f;
#pragma unroll 4
        for (int s = 0; s < TT; s++)
            a = fmaf(sc[s], hc[s * CC + tid], a);
        ws[tid] = a;
    }
    __syncthreads();

    // ---- ctx_j = (Wv^T wsum)_j / denom + bv_j ----
    if (tid < CC) {
        float a = 0.f;
#pragma unroll 4
        for (int c = 0; c < CC; c++)
            a = fmaf(ws[c], __ldg(Wv + c * CC + tid), a);
        g_last[(size_t)seq * CC + tid] = a / red[0] + __ldg(bv + tid);
    }
}

// ---------------------------------------------------------------------------
// Kernel 2: batched MLP (unchanged — known good)
// ---------------------------------------------------------------------------
__global__ void __launch_bounds__(128) mlp_kernel(
    const float* __restrict__ W1, const float* __restrict__ b1,
    const float* __restrict__ W2, const float* __restrict__ b2,
    const float* __restrict__ W3, const float* __restrict__ b3,
    float* __restrict__ out)
{
    __shared__ float sm[4 * 1536];
    const int warp = threadIdx.x >> 5, lane = threadIdx.x & 31;
    float* z1s = sm + warp * 1536;
    float* z2s = z1s + 1024;

    const int batch = blockIdx.x * 4 + warp;
    const int row0 = batch * 4;

    float al0[4], al1[4];
#pragma unroll
    for (int r = 0; r < 4; r++) {
        al0[r] = g_last[(size_t)(row0 + r) * CC + lane];
        al1[r] = g_last[(size_t)(row0 + r) * CC + 32 + lane];
    }

    {
        float acc[4][8];
#pragma unroll
        for (int jj = 0; jj < 8; jj++) {
            float bb = __ldg(b1 + lane + 32 * jj);
#pragma unroll
            for (int r = 0; r < 4; r++) acc[r][jj] = bb;
        }
#pragma unroll 4
        for (int k = 0; k < 32; k++) {
            float w[8];
#pragma unroll
            for (int jj = 0; jj < 8; jj++) w[jj] = __ldg(W1 + k * H1 + lane + 32 * jj);
            float av[4];
#pragma unroll
            for (int r = 0; r < 4; r++) av[r] = __shfl_sync(0xffffffffu, al0[r], k);
#pragma unroll
            for (int r = 0; r < 4; r++)
#pragma unroll
                for (int jj = 0; jj < 8; jj++) acc[r][jj] = fmaf(av[r], w[jj], acc[r][jj]);
        }
#pragma unroll 4
        for (int k = 0; k < 32; k++) {
            float w[8];
#pragma unroll
            for (int jj = 0; jj < 8; jj++) w[jj] = __ldg(W1 + (k + 32) * H1 + lane + 32 * jj);
            float av[4];
#pragma unroll
            for (int r = 0; r < 4; r++) av[r] = __shfl_sync(0xffffffffu, al1[r], k);
#pragma unroll
            for (int r = 0; r < 4; r++)
#pragma unroll
                for (int jj = 0; jj < 8; jj++) acc[r][jj] = fmaf(av[r], w[jj], acc[r][jj]);
        }
#pragma unroll
        for (int r = 0; r < 4; r++)
#pragma unroll
            for (int jj = 0; jj < 8; jj++)
                z1s[r * H1 + lane + 32 * jj] = fmaxf(acc[r][jj], 0.f);
        __syncwarp();
    }

    {
        float acc[4][4];
#pragma unroll
        for (int jj = 0; jj < 4; jj++) {
            float bb = __ldg(b2 + lane + 32 * jj);
#pragma unroll
            for (int r = 0; r < 4; r++) acc[r][jj] = bb;
        }
#pragma unroll 4
        for (int k = 0; k < H1; k++) {
            float w[4];
#pragma unroll
            for (int jj = 0; jj < 4; jj++) w[jj] = __ldg(W2 + k * H2 + lane + 32 * jj);
            float zv[4];
#pragma unroll
            for (int r = 0; r < 4; r++) zv[r] = z1s[r * H1 + k];
#pragma unroll
            for (int r = 0; r < 4; r++)
#pragma unroll
                for (int jj = 0; jj < 4; jj++) acc[r][jj] = fmaf(zv[r], w[jj], acc[r][jj]);
        }
#pragma unroll
        for (int r = 0; r < 4; r++)
#pragma unroll
            for (int jj = 0; jj < 4; jj++)
                z2s[r * H2 + lane + 32 * jj] = fmaxf(acc[r][jj], 0.f);
        __syncwarp();
    }

#pragma unroll
    for (int r = 0; r < 4; r++) {
        if (lane < NPRED) {
            float a = __ldg(b3 + lane);
#pragma unroll 4
            for (int k = 0; k < H2; k++)
                a = fmaf(z2s[r * H2 + k], __ldg(W3 + k * NPRED + lane), a);
            const int row = row0 + r;
            const int b = row >> 11;
            const int n = row & 2047;
            out[(size_t)b * (NPRED * NN) + (size_t)lane * NN + n] = a;
        }
    }
}

// ---------------------------------------------------------------------------
extern "C" void kernel_launch(void* const* d_in, const int* in_sizes, int n_in,
                              void* d_out, int out_size) {
    const float* x      = (const float*)d_in[0];
    const float* W_in   = (const float*)d_in[1];
    const float* b_in   = (const float*)d_in[2];
    const float* W_conv = (const float*)d_in[3];
    const float* b_conv = (const float*)d_in[4];
    const float* Wq     = (const float*)d_in[5];
    const float* bq     = (const float*)d_in[6];
    const float* Wk     = (const float*)d_in[7];
    const float* bk     = (const float*)d_in[8];
    const float* Wv     = (const float*)d_in[9];
    const float* bv     = (const float*)d_in[10];
    const float* W1     = (const float*)d_in[11];
    const float* b1     = (const float*)d_in[12];
    const float* W2     = (const float*)d_in[13];
    const float* b2     = (const float*)d_in[14];
    const float* W3     = (const float*)d_in[15];
    const float* b3     = (const float*)d_in[16];
    float* out = (float*)d_out;

    prep_kernel<<<24, 256>>>(W_in, W_conv, b_in, b_conv, Wq, bq, Wk, bk);
    seq_kernel<<<NSEQ, 128>>>(x, Wv, bv);
    mlp_kernel<<<NSEQ / 16, 128>>>(W1, b1, W2, b2, W3, b3, out);
}

// round 13
// speedup vs baseline: 7.6862x; 1.2152x over previous
#include <cuda_runtime.h>
#include <cuda_bf16.h>

// ---------------- problem constants ----------------
#define BB   16
#define NN   2048
#define NSEQ (BB*NN)      // 32768
#define TT   48
#define EE   32
#define CC   64
#define H1   256
#define H2   128
#define NPRED 12

// ---------------- device scratch ----------------
__device__ float g_last[NSEQ * CC];
// composite conv weights, pre-swizzled B-fragments (hi/lo bf16): 6 ksteps x 8 nb x 32 lanes
__device__ uint2 g_Bh2[6 * 8 * 32];
__device__ uint2 g_Bl2[6 * 8 * 32];
__device__ float g_bias[3 * CC];    // [0]=t0, [1]=interior, [2]=t47
__device__ float g_M[CC * CC];      // M[e][c] = sum_j Wq[e,j] Wk[c,j]
__device__ float g_vkb[CC];         // Wk . bq
__device__ float g_wqbk[CC];        // Wq . bk
__device__ float g_bqbk[1];         // bq . bk
// MLP weight fragments (hi/lo bf16): W1 4 ksteps x 32 nb, W2 16 ksteps x 16 nb
__device__ uint2 g_B1h2[4 * 32 * 32];
__device__ uint2 g_B1l2[4 * 32 * 32];
__device__ uint2 g_B2h2[16 * 16 * 32];
__device__ uint2 g_B2l2[16 * 16 * 32];

// ---------------- helpers ----------------
__device__ __forceinline__ unsigned short f2bf(float f) {
    __nv_bfloat16 h = __float2bfloat16(f);
    return *reinterpret_cast<unsigned short*>(&h);
}
__device__ __forceinline__ float bf2f(unsigned short u) {
    __nv_bfloat16 h = *reinterpret_cast<__nv_bfloat16*>(&u);
    return __bfloat162float(h);
}
__device__ __forceinline__ unsigned scvta(const void* p) {
    return (unsigned)__cvta_generic_to_shared(p);
}
__device__ __forceinline__ void ldsm4(unsigned a[4], unsigned saddr) {
    asm volatile("ldmatrix.sync.aligned.m8n8.x4.shared.b16 {%0,%1,%2,%3},[%4];"
                 : "=r"(a[0]), "=r"(a[1]), "=r"(a[2]), "=r"(a[3]) : "r"(saddr));
}
__device__ __forceinline__ void mma_bf16(float* c, const unsigned a[4], uint2 b) {
    asm volatile(
        "mma.sync.aligned.m16n8k16.row.col.f32.bf16.bf16.f32 "
        "{%0,%1,%2,%3},{%4,%5,%6,%7},{%8,%9},{%0,%1,%2,%3};"
        : "+f"(c[0]), "+f"(c[1]), "+f"(c[2]), "+f"(c[3])
        : "r"(a[0]), "r"(a[1]), "r"(a[2]), "r"(a[3]), "r"(b.x), "r"(b.y));
}
__device__ __forceinline__ void st_split(unsigned short* H, unsigned short* L, int idx, float v) {
    unsigned short h = f2bf(v);
    H[idx] = h;
    L[idx] = f2bf(v - bf2f(h));
}

// ---------------------------------------------------------------------------
// prep: composite conv weights, attention-fold matrices, and MLP weight
// fragments. index map:
//   [0,1536) conv frags | [1536,1728) bias | [1728,5824) M | [5824,5888) vkb
//   [5888,5952) wqbk | [5952] bqbk | [6144,10240) W1 frags | [10240,18432) W2
// ---------------------------------------------------------------------------
__global__ void prep_kernel(const float* __restrict__ W_in,
                            const float* __restrict__ W_conv,
                            const float* __restrict__ b_in,
                            const float* __restrict__ b_conv,
                            const float* __restrict__ Wq,
                            const float* __restrict__ bq,
                            const float* __restrict__ Wk,
                            const float* __restrict__ bk,
                            const float* __restrict__ W1,
                            const float* __restrict__ W2)
{
    int idx = blockIdx.x * 256 + threadIdx.x;

    if (idx < 1536) {
        int lane = idx & 31;
        int nb   = (idx >> 5) & 7;
        int ks   = idx >> 8;          // 0..5
        int d    = ks >> 1;
        int kb   = (ks & 1) * 16;
        int n    = nb * 8 + (lane >> 2);
        const float* Wc = W_conv + d * (CC * CC);

        unsigned hi[2], lo[2];
#pragma unroll
        for (int r = 0; r < 2; r++) {
            int k = kb + (lane & 3) * 2 + r * 8;
            float w0 = 0.f, w1 = 0.f;
#pragma unroll 4
            for (int c = 0; c < CC; c++) {
                float wc = Wc[c * CC + n];
                w0 = fmaf(W_in[k * CC + c], wc, w0);
                w1 = fmaf(W_in[(k + 1) * CC + c], wc, w1);
            }
            unsigned short h0 = f2bf(w0), h1 = f2bf(w1);
            unsigned short l0 = f2bf(w0 - bf2f(h0)), l1 = f2bf(w1 - bf2f(h1));
            hi[r] = (unsigned)h0 | ((unsigned)h1 << 16);
            lo[r] = (unsigned)l0 | ((unsigned)l1 << 16);
        }
        int o = (ks * 8 + nb) * 32 + lane;
        g_Bh2[o] = make_uint2(hi[0], hi[1]);
        g_Bl2[o] = make_uint2(lo[0], lo[1]);
    }
    else if (idx < 1728) {
        int i = idx - 1536;
        int which = i >> 6;           // 0=t0, 1=mid, 2=t47
        int n = i & 63;
        float s0 = 0.f, s1 = 0.f, s2 = 0.f;
#pragma unroll 4
        for (int c = 0; c < CC; c++) {
            float bc = b_in[c];
            s0 = fmaf(bc, W_conv[(0 * CC + c) * CC + n], s0);
            s1 = fmaf(bc, W_conv[(1 * CC + c) * CC + n], s1);
            s2 = fmaf(bc, W_conv[(2 * CC + c) * CC + n], s2);
        }
        float v = b_conv[n];
        if (which == 0)      v += s1 + s2;       // t=0: tap 0 missing
        else if (which == 1) v += s0 + s1 + s2;  // interior
        else                 v += s0 + s1;       // t=47: tap 2 missing
        g_bias[which * CC + n] = v;
    }
    else if (idx < 5824) {
        int i = idx - 1728;
        int e = i >> 6, c = i & 63;
        float a = 0.f;
#pragma unroll 4
        for (int j = 0; j < CC; j++)
            a = fmaf(Wq[e * CC + j], Wk[c * CC + j], a);
        g_M[e * CC + c] = a;
    }
    else if (idx < 5888) {
        int c = idx - 5824;
        float a = 0.f;
#pragma unroll 4
        for (int j = 0; j < CC; j++)
            a = fmaf(Wk[c * CC + j], bq[j], a);
        g_vkb[c] = a;
    }
    else if (idx < 5952) {
        int e = idx - 5888;
        float a = 0.f;
#pragma unroll 4
        for (int j = 0; j < CC; j++)
            a = fmaf(Wq[e * CC + j], bk[j], a);
        g_wqbk[e] = a;
    }
    else if (idx == 5952) {
        float a = 0.f;
#pragma unroll 4
        for (int j = 0; j < CC; j++)
            a = fmaf(bq[j], bk[j], a);
        g_bqbk[0] = a;
    }
    else if (idx >= 6144 && idx < 10240) {
        // W1 fragments: K=64 (4 ksteps), N=256 (32 nb)
        int i = idx - 6144;
        int lane = i & 31;
        int nb   = (i >> 5) & 31;
        int ks   = i >> 10;           // 0..3
        int n    = nb * 8 + (lane >> 2);
        unsigned hi[2], lo[2];
#pragma unroll
        for (int r = 0; r < 2; r++) {
            int k = ks * 16 + (lane & 3) * 2 + r * 8;
            float w0 = W1[k * H1 + n];
            float w1 = W1[(k + 1) * H1 + n];
            unsigned short h0 = f2bf(w0), h1 = f2bf(w1);
            unsigned short l0 = f2bf(w0 - bf2f(h0)), l1 = f2bf(w1 - bf2f(h1));
            hi[r] = (unsigned)h0 | ((unsigned)h1 << 16);
            lo[r] = (unsigned)l0 | ((unsigned)l1 << 16);
        }
        int o = (ks * 32 + nb) * 32 + lane;
        g_B1h2[o] = make_uint2(hi[0], hi[1]);
        g_B1l2[o] = make_uint2(lo[0], lo[1]);
    }
    else if (idx >= 10240 && idx < 18432) {
        // W2 fragments: K=256 (16 ksteps), N=128 (16 nb)
        int i = idx - 10240;
        int lane = i & 31;
        int nb   = (i >> 5) & 15;
        int ks   = i >> 9;            // 0..15
        int n    = nb * 8 + (lane >> 2);
        unsigned hi[2], lo[2];
#pragma unroll
        for (int r = 0; r < 2; r++) {
            int k = ks * 16 + (lane & 3) * 2 + r * 8;
            float w0 = W2[k * H2 + n];
            float w1 = W2[(k + 1) * H2 + n];
            unsigned short h0 = f2bf(w0), h1 = f2bf(w1);
            unsigned short l0 = f2bf(w0 - bf2f(h0)), l1 = f2bf(w1 - bf2f(h1));
            hi[r] = (unsigned)h0 | ((unsigned)h1 << 16);
            lo[r] = (unsigned)l0 | ((unsigned)l1 << 16);
        }
        int o = (ks * 16 + nb) * 32 + lane;
        g_B2h2[o] = make_uint2(hi[0], hi[1]);
        g_B2l2[o] = make_uint2(lo[0], lo[1]);
    }
}

// ---------------------------------------------------------------------------
// Kernel 1: per-sequence fused pipeline (UNCHANGED from R12 — known good)
// ---------------------------------------------------------------------------
__global__ void __launch_bounds__(128) seq_kernel(
    const float* __restrict__ x,
    const float* __restrict__ Wv,
    const float* __restrict__ bv)
{
    __shared__ __align__(16) unsigned char smraw[21024];
    unsigned short* xh  = (unsigned short*)smraw;              // [50][40] (rows 0,49 zero)
    unsigned short* xl  = (unsigned short*)(smraw + 4000);     // [50][40]
    float*          hc  = (float*)(smraw + 8000);              // [48][64] fp32
    float*          us  = (float*)(smraw + 20288);             // [64]
    float*          ws  = (float*)(smraw + 20544);             // [64] wsum
    float*          sc  = (float*)(smraw + 20800);             // [48]
    float*          red = (float*)(smraw + 20992);             // [0]=denom [1]=qconst

    const int tid  = threadIdx.x;
    const int lane = tid & 31;
    const int warp = tid >> 5;
    const int seq  = blockIdx.x;

    const float* xg = x + (size_t)seq * (TT * EE);
#pragma unroll
    for (int i = tid; i < TT * EE; i += 128) {
        int row = (i >> 5) + 1, col = i & 31;
        float v = xg[i];
        unsigned short h = f2bf(v);
        xh[row * 40 + col] = h;
        xl[row * 40 + col] = f2bf(v - bf2f(h));
    }
    if (tid < 32) {
        xh[tid] = 0; xl[tid] = 0;
        xh[49 * 40 + tid] = 0; xl[49 * 40 + tid] = 0;
    }
    __syncthreads();

    const int R     = lane >> 2;
    const int Cb    = warp * 16;
    const int row_l = (lane & 7) | (((lane >> 3) & 1) << 3);
    const int col_l = (lane >> 4) << 3;

    float acc[3][2][4];
#pragma unroll
    for (int m = 0; m < 3; m++)
#pragma unroll
        for (int n = 0; n < 2; n++)
#pragma unroll
            for (int i = 0; i < 4; i++) acc[m][n][i] = 0.f;

#pragma unroll
    for (int d = 0; d < 3; d++) {
#pragma unroll
        for (int ks = 0; ks < 2; ks++) {
            int bidx = ((d * 2 + ks) * 8 + 2 * warp) * 32 + lane;
            uint2 bh0 = __ldg(&g_Bh2[bidx]);
            uint2 bh1 = __ldg(&g_Bh2[bidx + 32]);
            uint2 bl0 = __ldg(&g_Bl2[bidx]);
            uint2 bl1 = __ldg(&g_Bl2[bidx + 32]);
#pragma unroll
            for (int mb = 0; mb < 3; mb++) {
                int aoff = (d + mb * 16 + row_l) * 40 + ks * 16 + col_l;
                unsigned ah[4], al[4];
                ldsm4(ah, scvta(xh + aoff));
                ldsm4(al, scvta(xl + aoff));
                mma_bf16(acc[mb][0], ah, bh0);
                mma_bf16(acc[mb][0], ah, bl0);
                mma_bf16(acc[mb][0], al, bh0);
                mma_bf16(acc[mb][1], ah, bh1);
                mma_bf16(acc[mb][1], ah, bl1);
                mma_bf16(acc[mb][1], al, bh1);
            }
        }
    }

#pragma unroll
    for (int nb = 0; nb < 2; nb++) {
        int C0 = Cb + nb * 8 + (lane & 3) * 2;
#pragma unroll
        for (int mb = 0; mb < 3; mb++) {
            int r0 = mb * 16 + R, r1 = r0 + 8;
            const float* bp0 = g_bias + ((r0 == 0) ? 0 : CC);
            const float* bp1 = g_bias + ((r1 == 47) ? 2 * CC : CC);
            float2 v0, v1;
            v0.x = fmaxf(acc[mb][nb][0] + bp0[C0],     0.f);
            v0.y = fmaxf(acc[mb][nb][1] + bp0[C0 + 1], 0.f);
            v1.x = fmaxf(acc[mb][nb][2] + bp1[C0],     0.f);
            v1.y = fmaxf(acc[mb][nb][3] + bp1[C0 + 1], 0.f);
            *reinterpret_cast<float2*>(&hc[r0 * CC + C0]) = v0;
            *reinterpret_cast<float2*>(&hc[r1 * CC + C0]) = v1;
        }
    }
    __syncthreads();

    if (tid < CC) {
        float a = g_vkb[tid];
#pragma unroll 4
        for (int e = 0; e < CC; e++)
            a = fmaf(hc[47 * CC + e], __ldg(&g_M[e * CC + tid]), a);
        us[tid] = a;
    } else if (warp == 2) {
        float p = hc[47 * CC + lane] * g_wqbk[lane]
                + hc[47 * CC + lane + 32] * g_wqbk[lane + 32];
#pragma unroll
        for (int off = 16; off > 0; off >>= 1)
            p += __shfl_xor_sync(0xffffffffu, p, off);
        if (lane == 0) red[1] = p + g_bqbk[0];
    }
    __syncthreads();

    {
        float qc = red[1];
        for (int s = warp; s < TT; s += 4) {
            float p = us[lane] * hc[s * CC + lane]
                    + us[lane + 32] * hc[s * CC + lane + 32];
#pragma unroll
            for (int off = 16; off > 0; off >>= 1)
                p += __shfl_xor_sync(0xffffffffu, p, off);
            if (lane == 0) sc[s] = (p + qc) * 0.125f;
        }
    }
    __syncthreads();

    if (tid < 32) {
        float v1 = sc[tid];
        float v2 = (tid < 16) ? sc[32 + tid] : -3.4e38f;
        float m = fmaxf(v1, v2);
#pragma unroll
        for (int off = 16; off > 0; off >>= 1)
            m = fmaxf(m, __shfl_xor_sync(0xffffffffu, m, off));
        float e1 = __expf(v1 - m);
        float e2 = (tid < 16) ? __expf(v2 - m) : 0.f;
        float ssum = e1 + e2;
#pragma unroll
        for (int off = 16; off > 0; off >>= 1)
            ssum += __shfl_xor_sync(0xffffffffu, ssum, off);
        sc[tid] = e1;
        if (tid < 16) sc[32 + tid] = e2;
        if (tid == 0) red[0] = ssum;
    }
    __syncthreads();

    if (tid < CC) {
        float a = 0.f;
#pragma unroll 4
        for (int s = 0; s < TT; s++)
            a = fmaf(sc[s], hc[s * CC + tid], a);
        ws[tid] = a;
    }
    __syncthreads();

    if (tid < CC) {
        float a = 0.f;
#pragma unroll 4
        for (int c = 0; c < CC; c++)
            a = fmaf(ws[c], __ldg(Wv + c * CC + tid), a);
        g_last[(size_t)seq * CC + tid] = a / red[0] + __ldg(bv + tid);
    }
}

// ---------------------------------------------------------------------------
// Kernel 2: batched MLP via bf16x3 tensor-core GEMM.
// One CTA = 16 rows. L1: 16x256 (K=64), L2: 16x128 (K=256) mma; L3 scalar.
// ---------------------------------------------------------------------------
__global__ void __launch_bounds__(128) mlp_kernel(
    const float* __restrict__ b1, const float* __restrict__ b2,
    const float* __restrict__ W3, const float* __restrict__ b3,
    float* __restrict__ out)
{
    __shared__ __align__(16) unsigned char smraw[29696];
    unsigned short* inh = (unsigned short*)smraw;             // [16][72]
    unsigned short* inl = (unsigned short*)(smraw + 2304);    // [16][72]
    unsigned short* z1h = (unsigned short*)(smraw + 4608);    // [16][264]
    unsigned short* z1l = (unsigned short*)(smraw + 13056);   // [16][264]
    float*          z2  = (float*)(smraw + 21504);            // [16][128]

    const int tid  = threadIdx.x;
    const int lane = tid & 31;
    const int warp = tid >> 5;
    const int row0 = blockIdx.x * 16;

    // ---- load + split input rows ----
#pragma unroll
    for (int i = tid; i < 16 * CC; i += 128) {
        int r = i >> 6, c = i & 63;
        float v = g_last[(size_t)(row0 + r) * CC + c];
        unsigned short h = f2bf(v);
        inh[r * 72 + c] = h;
        inl[r * 72 + c] = f2bf(v - bf2f(h));
    }
    __syncthreads();

    const int R     = lane >> 2;
    const int row_l = (lane & 7) | (((lane >> 3) & 1) << 3);
    const int col_l = (lane >> 4) << 3;

    // ---- layer 1: 16x256 = in(16x64) @ W1, warp owns 64 cols ----
    {
        float acc[8][4];
#pragma unroll
        for (int p = 0; p < 8; p++)
#pragma unroll
            for (int i = 0; i < 4; i++) acc[p][i] = 0.f;

#pragma unroll
        for (int ks = 0; ks < 4; ks++) {
            unsigned ah[4], al[4];
            ldsm4(ah, scvta(inh + row_l * 72 + ks * 16 + col_l));
            ldsm4(al, scvta(inl + row_l * 72 + ks * 16 + col_l));
#pragma unroll
            for (int p = 0; p < 4; p++) {
                int bidx = (ks * 32 + warp * 8 + 2 * p) * 32 + lane;
                uint2 bh0 = __ldg(&g_B1h2[bidx]);
                uint2 bh1 = __ldg(&g_B1h2[bidx + 32]);
                uint2 bl0 = __ldg(&g_B1l2[bidx]);
                uint2 bl1 = __ldg(&g_B1l2[bidx + 32]);
                mma_bf16(acc[2 * p],     ah, bh0);
                mma_bf16(acc[2 * p],     ah, bl0);
                mma_bf16(acc[2 * p],     al, bh0);
                mma_bf16(acc[2 * p + 1], ah, bh1);
                mma_bf16(acc[2 * p + 1], ah, bl1);
                mma_bf16(acc[2 * p + 1], al, bh1);
            }
        }
        // epilogue: bias + relu -> z1 split
#pragma unroll
        for (int p = 0; p < 8; p++) {
            int C = warp * 64 + p * 8 + (lane & 3) * 2;
            float bb0 = __ldg(b1 + C), bb1 = __ldg(b1 + C + 1);
            st_split(z1h, z1l, R * 264 + C,           fmaxf(acc[p][0] + bb0, 0.f));
            st_split(z1h, z1l, R * 264 + C + 1,       fmaxf(acc[p][1] + bb1, 0.f));
            st_split(z1h, z1l, (R + 8) * 264 + C,     fmaxf(acc[p][2] + bb0, 0.f));
            st_split(z1h, z1l, (R + 8) * 264 + C + 1, fmaxf(acc[p][3] + bb1, 0.f));
        }
    }
    __syncthreads();

    // ---- layer 2: 16x128 = z1(16x256) @ W2, warp owns 32 cols ----
    {
        float acc[4][4];
#pragma unroll
        for (int p = 0; p < 4; p++)
#pragma unroll
            for (int i = 0; i < 4; i++) acc[p][i] = 0.f;

#pragma unroll
        for (int ks = 0; ks < 16; ks++) {
            unsigned ah[4], al[4];
            ldsm4(ah, scvta(z1h + row_l * 264 + ks * 16 + col_l));
            ldsm4(al, scvta(z1l + row_l * 264 + ks * 16 + col_l));
#pragma unroll
            for (int p = 0; p < 2; p++) {
                int bidx = (ks * 16 + warp * 4 + 2 * p) * 32 + lane;
                uint2 bh0 = __ldg(&g_B2h2[bidx]);
                uint2 bh1 = __ldg(&g_B2h2[bidx + 32]);
                uint2 bl0 = __ldg(&g_B2l2[bidx]);
                uint2 bl1 = __ldg(&g_B2l2[bidx + 32]);
                mma_bf16(acc[2 * p],     ah, bh0);
                mma_bf16(acc[2 * p],     ah, bl0);
                mma_bf16(acc[2 * p],     al, bh0);
                mma_bf16(acc[2 * p + 1], ah, bh1);
                mma_bf16(acc[2 * p + 1], ah, bl1);
                mma_bf16(acc[2 * p + 1], al, bh1);
            }
        }
        // epilogue: bias + relu -> z2 fp32
#pragma unroll
        for (int p = 0; p < 4; p++) {
            int C = warp * 32 + p * 8 + (lane & 3) * 2;
            float bb0 = __ldg(b2 + C), bb1 = __ldg(b2 + C + 1);
            z2[R * 128 + C]           = fmaxf(acc[p][0] + bb0, 0.f);
            z2[R * 128 + C + 1]       = fmaxf(acc[p][1] + bb1, 0.f);
            z2[(R + 8) * 128 + C]     = fmaxf(acc[p][2] + bb0, 0.f);
            z2[(R + 8) * 128 + C + 1] = fmaxf(acc[p][3] + bb1, 0.f);
        }
    }
    __syncthreads();

    // ---- layer 3: 128 -> 12 scalar fp32, transposed store ----
    for (int t = tid; t < 16 * NPRED; t += 128) {
        int r = t / NPRED, o = t % NPRED;
        float a = __ldg(b3 + o);
        const float* z = z2 + r * 128;
#pragma unroll 4
        for (int k = 0; k < H2; k++)
            a = fmaf(z[k], __ldg(W3 + k * NPRED + o), a);
        int row = row0 + r;
        int b = row >> 11;
        int n = row & 2047;
        out[(size_t)b * (NPRED * NN) + (size_t)o * NN + n] = a;
    }
}

// ---------------------------------------------------------------------------
extern "C" void kernel_launch(void* const* d_in, const int* in_sizes, int n_in,
                              void* d_out, int out_size) {
    const float* x      = (const float*)d_in[0];
    const float* W_in   = (const float*)d_in[1];
    const float* b_in   = (const float*)d_in[2];
    const float* W_conv = (const float*)d_in[3];
    const float* b_conv = (const float*)d_in[4];
    const float* Wq     = (const float*)d_in[5];
    const float* bq     = (const float*)d_in[6];
    const float* Wk     = (const float*)d_in[7];
    const float* bk     = (const float*)d_in[8];
    const float* Wv     = (const float*)d_in[9];
    const float* bv     = (const float*)d_in[10];
    const float* W1     = (const float*)d_in[11];
    const float* b1     = (const float*)d_in[12];
    const float* W2     = (const float*)d_in[13];
    const float* b2     = (const float*)d_in[14];
    const float* W3     = (const float*)d_in[15];
    const float* b3     = (const float*)d_in[16];
    float* out = (float*)d_out;

    prep_kernel<<<72, 256>>>(W_in, W_conv, b_in, b_conv, Wq, bq, Wk, bk, W1, W2);
    seq_kernel<<<NSEQ, 128>>>(x, Wv, bv);
    mlp_kernel<<<NSEQ / 16, 128>>>(b1, b2, W3, b3, out);
}